// round 2
// baseline (speedup 1.0000x reference)
#include <cuda_runtime.h>

namespace {

constexpr int N = 8;      // seq len
constexpr int D = 12;     // embed dim
constexpr int F = 24;     // ff dim
constexpr int V = 128;    // vocab
constexpr int WARPS = 8;  // warps (= items) per block
constexpr int THREADS = WARPS * 32;

constexpr int RS = 12;    // row stride for D-wide rows (banks rotate by 12)
constexpr int SS = 12;    // padded S row stride (8 used)
constexpr int HS = 28;    // padded H row stride (24 used, banks rotate by 28)

#define F4C(p) (*reinterpret_cast<const float4*>(p))
#define F4(p)  (*reinterpret_cast<float4*>(p))

using ull = unsigned long long;

__device__ __forceinline__ ull pack2(float x, float y) {
    ull p;
    asm("mov.b64 %0, {%1, %2};" : "=l"(p) : "f"(x), "f"(y));
    return p;
}
__device__ __forceinline__ void unpack2(ull p, float& x, float& y) {
    asm("mov.b64 {%0, %1}, %2;" : "=f"(x), "=f"(y) : "l"(p));
}
__device__ __forceinline__ void ffma2(ull& d, ull a, ull b) {
    asm("fma.rn.f32x2 %0, %1, %2, %0;" : "+l"(d) : "l"(a), "l"(b));
}

// load a 12-float (3x float4) row from smem into registers
__device__ __forceinline__ void ldrow12(const float* __restrict__ s, float* __restrict__ r) {
    float4 a = F4C(s), b = F4C(s + 4), c = F4C(s + 8);
    r[0]=a.x; r[1]=a.y; r[2]=a.z;  r[3]=a.w;
    r[4]=b.x; r[5]=b.y; r[6]=b.z;  r[7]=b.w;
    r[8]=c.x; r[9]=c.y; r[10]=c.z; r[11]=c.w;
}

// dot(r[0..11], smem row w) with vector loads
__device__ __forceinline__ float dot12(const float* __restrict__ r, const float* __restrict__ w) {
    float4 w0 = F4C(w), w1 = F4C(w + 4), w2 = F4C(w + 8);
    float acc;
    acc  = r[0]*w0.x;  acc += r[1]*w0.y;  acc += r[2]*w0.z;  acc += r[3]*w0.w;
    acc += r[4]*w1.x;  acc += r[5]*w1.y;  acc += r[6]*w1.z;  acc += r[7]*w1.w;
    acc += r[8]*w2.x;  acc += r[9]*w2.y;  acc += r[10]*w2.z; acc += r[11]*w2.w;
    return acc;
}

// dot(r[0..23], smem row w) with vector loads
__device__ __forceinline__ float dot24(const float* __restrict__ r, const float* __restrict__ w) {
    float acc = 0.f;
    #pragma unroll
    for (int k = 0; k < 6; k++) {
        float4 wk = F4C(w + 4 * k);
        acc += r[4*k+0]*wk.x; acc += r[4*k+1]*wk.y;
        acc += r[4*k+2]*wk.z; acc += r[4*k+3]*wk.w;
    }
    return acc;
}

__global__ __launch_bounds__(THREADS, 3)
void tiny_transformer_kernel(
    const int*   __restrict__ x,
    const float* __restrict__ embed,
    const float* __restrict__ pos,
    const float* __restrict__ Wq, const float* __restrict__ bq,
    const float* __restrict__ Wk, const float* __restrict__ bk,
    const float* __restrict__ Wv, const float* __restrict__ bv,
    const float* __restrict__ Wo, const float* __restrict__ bo,
    const float* __restrict__ W1, const float* __restrict__ b1,
    const float* __restrict__ W2, const float* __restrict__ b2,
    const float* __restrict__ blm,
    float* __restrict__ out)
{
    // ---- block-shared weights ----
    __shared__ __align__(16) float sEmb[V * D];    // natural [v][d]
    __shared__ __align__(16) float sEmbT[D * V];   // transposed [d][v]
    __shared__ __align__(16) float sPos[N * D];
    __shared__ __align__(16) float sWq[D * D], sWk[D * D], sWv[D * D], sWo[D * D];
    __shared__ __align__(16) float sW1[F * D];
    __shared__ __align__(16) float sW2[D * F];
    __shared__ __align__(16) float sBq[D], sBk[D], sBv[D], sBo[D], sB2[D];
    __shared__ __align__(16) float sB1[F];
    __shared__ __align__(16) float sBlm[V];

    // ---- per-warp scratch ----
    __shared__ __align__(16) float sX[WARPS][N * RS];
    __shared__ __align__(16) float sQ[WARPS][N * RS];
    __shared__ __align__(16) float sK[WARPS][N * RS];
    __shared__ __align__(16) float sV[WARPS][N * RS];
    __shared__ __align__(16) float sA[WARPS][N * RS];
    __shared__ __align__(16) float sS[WARPS][N * SS];
    __shared__ __align__(16) float sH[WARPS][N * HS];
    __shared__ int sTok[WARPS][N];

    const int tid = threadIdx.x;

    // cooperative weight staging
    for (int i = tid; i < V * D; i += THREADS) sEmb[i] = embed[i];
    for (int i = tid; i < D * V; i += THREADS) {
        int d = i / V, v = i % V;
        sEmbT[i] = embed[v * D + d];
    }
    for (int i = tid; i < N * D; i += THREADS) sPos[i] = pos[i];
    for (int i = tid; i < D * D; i += THREADS) {
        sWq[i] = Wq[i]; sWk[i] = Wk[i]; sWv[i] = Wv[i]; sWo[i] = Wo[i];
    }
    for (int i = tid; i < D; i += THREADS) {
        sBq[i] = bq[i]; sBk[i] = bk[i]; sBv[i] = bv[i]; sBo[i] = bo[i]; sB2[i] = b2[i];
    }
    for (int i = tid; i < F * D; i += THREADS) { sW1[i] = W1[i]; sW2[i] = W2[i]; }
    for (int i = tid; i < F; i += THREADS) sB1[i] = b1[i];
    for (int i = tid; i < V; i += THREADS) sBlm[i] = blm[i];
    __syncthreads();

    const int w    = tid >> 5;
    const int lane = tid & 31;
    const int item = blockIdx.x * WARPS + w;

    float* X  = sX[w];
    float* Q  = sQ[w];
    float* K  = sK[w];
    float* Vv = sV[w];
    float* S  = sS[w];
    float* A  = sA[w];
    float* H  = sH[w];

    if (lane < N) sTok[w][lane] = x[item * N + lane];
    __syncwarp();

    // ---- phase 1: X = embed[x] + pos  (24 float4 outputs) ----
    if (lane < 24) {
        const int n = lane / 3, g = lane % 3;
        const int tok = sTok[w][n];
        float4 e = F4C(&sEmb[tok * D + 4 * g]);
        float4 p = F4C(&sPos[n * D + 4 * g]);
        e.x += p.x; e.y += p.y; e.z += p.z; e.w += p.w;
        F4(&X[n * RS + 4 * g]) = e;
    }
    __syncwarp();

    // ---- phase 2: Q,K,V projections (3 scalar outputs per lane, row-cached) ----
    {
        float xr[12];
        #pragma unroll
        for (int k = 0; k < 3; k++) {
            const int o = lane + 32 * k;
            const int n = o / D, d = o % D;
            ldrow12(&X[n * RS], xr);
            Q[n * RS + d]  = sBq[d] + dot12(xr, &sWq[d * D]);
            K[n * RS + d]  = sBk[d] + dot12(xr, &sWk[d * D]);
            Vv[n * RS + d] = sBv[d] + dot12(xr, &sWv[d * D]);
        }
    }
    __syncwarp();

    // ---- phase 3: scores S[n][m] = <Q_n, K_m>/sqrt(D)  (2 outputs per lane) ----
    {
        const float inv_scale = 0.28867513459481287f;  // 1/sqrt(12)
        float qr[12];
        #pragma unroll
        for (int k = 0; k < 2; k++) {
            const int o = lane + 32 * k;
            const int n = o >> 3, m = o & 7;
            ldrow12(&Q[n * RS], qr);
            S[n * SS + m] = dot12(qr, &K[m * RS]) * inv_scale;
        }
    }
    __syncwarp();

    // ---- phase 4: causal softmax, lane n owns row n ----
    if (lane < N) {
        const int n = lane;
        float4 a = F4C(&S[n * SS]);
        float4 b = F4C(&S[n * SS + 4]);
        float sv[8] = {a.x, a.y, a.z, a.w, b.x, b.y, b.z, b.w};
        float mx = sv[0];
        for (int m = 1; m <= n; m++) mx = fmaxf(mx, sv[m]);
        float sum = 0.f;
        for (int m = 0; m <= n; m++) { sv[m] = __expf(sv[m] - mx); sum += sv[m]; }
        const float inv = 1.f / sum;
        #pragma unroll
        for (int m = 0; m < 8; m++) sv[m] = (m <= n) ? sv[m] * inv : 0.f;
        F4(&S[n * SS])     = make_float4(sv[0], sv[1], sv[2], sv[3]);
        F4(&S[n * SS + 4]) = make_float4(sv[4], sv[5], sv[6], sv[7]);
    }
    __syncwarp();

    // ---- phase 5: A = softmax @ V  (24 float4 outputs) ----
    if (lane < 24) {
        const int n = lane / 3, g = lane % 3;
        float4 acc = make_float4(0.f, 0.f, 0.f, 0.f);
        #pragma unroll
        for (int m = 0; m < N; m++) {
            const float s = S[n * SS + m];
            float4 v = F4C(&Vv[m * RS + 4 * g]);
            acc.x += s * v.x; acc.y += s * v.y; acc.z += s * v.z; acc.w += s * v.w;
        }
        F4(&A[n * RS + 4 * g]) = acc;
    }
    __syncwarp();

    // ---- phase 6: X += A @ Wo^T + bo  (24 float4 outputs) ----
    if (lane < 24) {
        const int n = lane / 3, g = lane % 3;
        float ar[12];
        ldrow12(&A[n * RS], ar);
        float4 acc = F4C(&sBo[4 * g]);
        acc.x += dot12(ar, &sWo[(4 * g + 0) * D]);
        acc.y += dot12(ar, &sWo[(4 * g + 1) * D]);
        acc.z += dot12(ar, &sWo[(4 * g + 2) * D]);
        acc.w += dot12(ar, &sWo[(4 * g + 3) * D]);
        float4 xv = F4C(&X[n * RS + 4 * g]);
        xv.x += acc.x; xv.y += acc.y; xv.z += acc.z; xv.w += acc.w;
        F4(&X[n * RS + 4 * g]) = xv;
    }
    __syncwarp();

    // ---- phase 7: H = relu(X @ W1^T + b1)  (48 float4 outputs, <=2/lane) ----
    {
        float xr[12];
        #pragma unroll
        for (int k = 0; k < 2; k++) {
            const int o = lane + 32 * k;
            if (o < 48) {
                const int n = o / 6, g = o % 6;
                ldrow12(&X[n * RS], xr);
                float4 acc = F4C(&sB1[4 * g]);
                acc.x += dot12(xr, &sW1[(4 * g + 0) * D]);
                acc.y += dot12(xr, &sW1[(4 * g + 1) * D]);
                acc.z += dot12(xr, &sW1[(4 * g + 2) * D]);
                acc.w += dot12(xr, &sW1[(4 * g + 3) * D]);
                acc.x = fmaxf(acc.x, 0.f); acc.y = fmaxf(acc.y, 0.f);
                acc.z = fmaxf(acc.z, 0.f); acc.w = fmaxf(acc.w, 0.f);
                F4(&H[n * HS + 4 * g]) = acc;
            }
        }
    }
    __syncwarp();

    // ---- phase 8: X += H @ W2^T + b2  (24 float4 outputs) ----
    if (lane < 24) {
        const int n = lane / 3, g = lane % 3;
        float hr[24];
        #pragma unroll
        for (int k = 0; k < 6; k++) {
            float4 h = F4C(&H[n * HS + 4 * k]);
            hr[4*k] = h.x; hr[4*k+1] = h.y; hr[4*k+2] = h.z; hr[4*k+3] = h.w;
        }
        float4 acc = F4C(&sB2[4 * g]);
        acc.x += dot24(hr, &sW2[(4 * g + 0) * F]);
        acc.y += dot24(hr, &sW2[(4 * g + 1) * F]);
        acc.z += dot24(hr, &sW2[(4 * g + 2) * F]);
        acc.w += dot24(hr, &sW2[(4 * g + 3) * F]);
        float4 xv = F4C(&X[n * RS + 4 * g]);
        xv.x += acc.x; xv.y += acc.y; xv.z += acc.z; xv.w += acc.w;
        F4(&X[n * RS + 4 * g]) = xv;
    }
    __syncwarp();

    // ---- phase 9: logits = X @ embed^T + b_lm  (packed f32x2 FMAs) ----
    {
        const int v0 = lane * 4;
        ull e01[D], e23[D];
        #pragma unroll
        for (int d = 0; d < D; d++) {
            float4 e = F4C(&sEmbT[d * V + v0]);
            e01[d] = pack2(e.x, e.y);
            e23[d] = pack2(e.z, e.w);
        }
        const float4 bl = F4C(&sBlm[v0]);
        const ull bl01 = pack2(bl.x, bl.y);
        const ull bl23 = pack2(bl.z, bl.w);

        float4* outp = reinterpret_cast<float4*>(out + (size_t)item * (N * V));
        #pragma unroll
        for (int n = 0; n < N; n++) {
            float xr[12];
            ldrow12(&X[n * RS], xr);   // broadcast loads
            ull a01 = bl01, a23 = bl23;
            #pragma unroll
            for (int d = 0; d < D; d++) {
                const ull xv2 = pack2(xr[d], xr[d]);
                ffma2(a01, xv2, e01[d]);
                ffma2(a23, xv2, e23[d]);
            }
            float4 acc;
            unpack2(a01, acc.x, acc.y);
            unpack2(a23, acc.z, acc.w);
            outp[n * (V / 4) + lane] = acc;
        }
    }
}

}  // namespace

extern "C" void kernel_launch(void* const* d_in, const int* in_sizes, int n_in,
                              void* d_out, int out_size)
{
    const int*   x     = (const int*)  d_in[0];
    const float* embed = (const float*)d_in[1];
    const float* pos   = (const float*)d_in[2];
    const float* Wq    = (const float*)d_in[3];
    const float* bq    = (const float*)d_in[4];
    const float* Wk    = (const float*)d_in[5];
    const float* bk    = (const float*)d_in[6];
    const float* Wv    = (const float*)d_in[7];
    const float* bv    = (const float*)d_in[8];
    const float* Wo    = (const float*)d_in[9];
    const float* bo    = (const float*)d_in[10];
    const float* W1    = (const float*)d_in[11];
    const float* b1    = (const float*)d_in[12];
    const float* W2    = (const float*)d_in[13];
    const float* b2    = (const float*)d_in[14];
    const float* blm   = (const float*)d_in[15];
    float* out = (float*)d_out;

    const int batch = in_sizes[0] / N;           // 32768
    const int blocks = batch / WARPS;            // 4096

    tiny_transformer_kernel<<<blocks, THREADS>>>(
        x, embed, pos, Wq, bq, Wk, bk, Wv, bv, Wo, bo,
        W1, b1, W2, b2, blm, out);
}

// round 3
// speedup vs baseline: 2.7067x; 2.7067x over previous
#include <cuda_runtime.h>

namespace {

constexpr int N = 8;      // seq len
constexpr int D = 12;     // embed dim
constexpr int F = 24;     // ff dim
constexpr int V = 128;    // vocab
constexpr int WARPS = 8;  // warps per block
constexpr int IPW = 4;    // items per warp (8 lanes each)
constexpr int THREADS = WARPS * 32;
constexpr int ITEMS_PER_BLOCK = WARPS * IPW;   // 32

#define F4C(p) (*reinterpret_cast<const float4*>(p))
#define F4(p)  (*reinterpret_cast<float4*>(p))

using ull = unsigned long long;

__device__ __forceinline__ ull pack2(float x, float y) {
    ull p; asm("mov.b64 %0, {%1, %2};" : "=l"(p) : "f"(x), "f"(y)); return p;
}
__device__ __forceinline__ void unpack2(ull p, float& x, float& y) {
    asm("mov.b64 {%0, %1}, %2;" : "=f"(x), "=f"(y) : "l"(p));
}
__device__ __forceinline__ void ffma2(ull& d, ull a, ull b) {
    asm("fma.rn.f32x2 %0, %1, %2, %0;" : "+l"(d) : "l"(a), "l"(b));
}

// dot of 12 register values against a 12-float smem row (broadcast LDS.128 x3)
__device__ __forceinline__ float dot12r(const float* __restrict__ r,
                                        const float* __restrict__ w) {
    float4 w0 = F4C(w), w1 = F4C(w + 4), w2 = F4C(w + 8);
    float acc;
    acc  = r[0]*w0.x;  acc += r[1]*w0.y;  acc += r[2]*w0.z;  acc += r[3]*w0.w;
    acc += r[4]*w1.x;  acc += r[5]*w1.y;  acc += r[6]*w1.z;  acc += r[7]*w1.w;
    acc += r[8]*w2.x;  acc += r[9]*w2.y;  acc += r[10]*w2.z; acc += r[11]*w2.w;
    return acc;
}

__device__ __forceinline__ float dot24r(const float* __restrict__ r,
                                        const float* __restrict__ w) {
    float acc = 0.f;
    #pragma unroll
    for (int k = 0; k < 6; k++) {
        float4 wk = F4C(w + 4 * k);
        acc += r[4*k+0]*wk.x; acc += r[4*k+1]*wk.y;
        acc += r[4*k+2]*wk.z; acc += r[4*k+3]*wk.w;
    }
    return acc;
}

__global__ __launch_bounds__(THREADS, 3)
void tiny_transformer_kernel(
    const int*   __restrict__ x,
    const float* __restrict__ embed,
    const float* __restrict__ pos,
    const float* __restrict__ Wq, const float* __restrict__ bq,
    const float* __restrict__ Wk, const float* __restrict__ bk,
    const float* __restrict__ Wv, const float* __restrict__ bv,
    const float* __restrict__ Wo, const float* __restrict__ bo,
    const float* __restrict__ W1, const float* __restrict__ b1,
    const float* __restrict__ W2, const float* __restrict__ b2,
    const float* __restrict__ blm,
    float* __restrict__ out)
{
    // ---- block-shared weights (read only as broadcasts or coalesced) ----
    __shared__ __align__(16) float sEmbT[D * V];   // transposed [d][v] for logits
    __shared__ __align__(16) float sWq[D * D], sWk[D * D], sWv[D * D], sWo[D * D];
    __shared__ __align__(16) float sW1[F * D];
    __shared__ __align__(16) float sW2[D * F];
    __shared__ __align__(16) float sBq[D], sBk[D], sBv[D], sBo[D], sB2[D];
    __shared__ __align__(16) float sB1[F];
    __shared__ __align__(16) float sBlm[V];
    // final hidden states handed to the logits phase: [warp][row(=g*8+n)][12]
    __shared__ __align__(16) float sXf[WARPS][IPW * N * D];

    const int tid = threadIdx.x;

    for (int i = tid; i < D * V; i += THREADS) {
        int d = i >> 7, v = i & 127;
        sEmbT[i] = embed[v * D + d];
    }
    for (int i = tid; i < D * D; i += THREADS) {
        sWq[i] = Wq[i]; sWk[i] = Wk[i]; sWv[i] = Wv[i]; sWo[i] = Wo[i];
    }
    for (int i = tid; i < D; i += THREADS) {
        sBq[i] = bq[i]; sBk[i] = bk[i]; sBv[i] = bv[i]; sBo[i] = bo[i]; sB2[i] = b2[i];
    }
    for (int i = tid; i < F * D; i += THREADS) { sW1[i] = W1[i]; sW2[i] = W2[i]; }
    for (int i = tid; i < F; i += THREADS) sB1[i] = b1[i];
    for (int i = tid; i < V; i += THREADS) sBlm[i] = blm[i];
    __syncthreads();

    const int w    = tid >> 5;
    const int lane = tid & 31;
    const int n    = lane & 7;            // token index within item
    const int item_base = blockIdx.x * ITEMS_PER_BLOCK + w * IPW;

    // ---- phase 1: X = embed[x] + pos (registers; coalesced token load) ----
    const int tok = __ldg(&x[item_base * N + lane]);   // 32 consecutive ints
    float X[D];
    {
        const float4* e4 = reinterpret_cast<const float4*>(embed);
        const float4* p4 = reinterpret_cast<const float4*>(pos);
        #pragma unroll
        for (int c = 0; c < 3; c++) {
            float4 e = __ldg(&e4[tok * 3 + c]);
            float4 p = __ldg(&p4[n * 3 + c]);
            X[4*c+0] = e.x + p.x; X[4*c+1] = e.y + p.y;
            X[4*c+2] = e.z + p.z; X[4*c+3] = e.w + p.w;
        }
    }

    // ---- phase 2: Q,K,V per token (weights broadcast from smem) ----
    float Qr[D], Kr[D], Vr[D];
    #pragma unroll
    for (int d = 0; d < D; d++) {
        Qr[d] = sBq[d] + dot12r(X, &sWq[d * D]);
        Kr[d] = sBk[d] + dot12r(X, &sWk[d * D]);
        Vr[d] = sBv[d] + dot12r(X, &sWv[d * D]);
    }

    // ---- phase 3: scores via width-8 shuffles ----
    float S[N];
    {
        const float inv_scale = 0.28867513459481287f;  // 1/sqrt(12)
        #pragma unroll
        for (int m = 0; m < N; m++) {
            float acc = 0.f;
            #pragma unroll
            for (int e = 0; e < D; e++)
                acc += Qr[e] * __shfl_sync(0xffffffffu, Kr[e], m, 8);
            S[m] = (m <= n) ? acc * inv_scale : -1e30f;
        }
    }

    // ---- phase 4: softmax over the register row ----
    {
        float mx = S[0];
        #pragma unroll
        for (int m = 1; m < N; m++) mx = fmaxf(mx, S[m]);
        float sum = 0.f;
        #pragma unroll
        for (int m = 0; m < N; m++) { S[m] = __expf(S[m] - mx); sum += S[m]; }
        const float inv = 1.f / sum;
        #pragma unroll
        for (int m = 0; m < N; m++) S[m] *= inv;   // masked entries ~0
    }

    // ---- phase 5: A = softmax @ V via shuffles ----
    float A[D];
    #pragma unroll
    for (int e = 0; e < D; e++) A[e] = 0.f;
    #pragma unroll
    for (int m = 0; m < N; m++) {
        const float s = S[m];
        #pragma unroll
        for (int e = 0; e < D; e++)
            A[e] += s * __shfl_sync(0xffffffffu, Vr[e], m, 8);
    }

    // ---- phase 6: X += A @ Wo^T + bo ----
    #pragma unroll
    for (int d = 0; d < D; d++)
        X[d] += sBo[d] + dot12r(A, &sWo[d * D]);

    // ---- phase 7: H = relu(X @ W1^T + b1) ----
    float H[F];
    #pragma unroll
    for (int f = 0; f < F; f++)
        H[f] = fmaxf(sB1[f] + dot12r(X, &sW1[f * D]), 0.f);

    // ---- phase 8: X += H @ W2^T + b2 ----
    #pragma unroll
    for (int d = 0; d < D; d++)
        X[d] += sB2[d] + dot24r(H, &sW2[d * F]);

    // ---- hand off final X to warp-wide logits phase ----
    {
        float* dst = &sXf[w][lane * D];
        F4(dst)     = make_float4(X[0], X[1], X[2],  X[3]);
        F4(dst + 4) = make_float4(X[4], X[5], X[6],  X[7]);
        F4(dst + 8) = make_float4(X[8], X[9], X[10], X[11]);
    }
    __syncwarp();

    // ---- phase 9: logits = Xf @ embed^T + b_lm (warp-wide, 32 rows) ----
    {
        const int v0 = lane * 4;
        ull e01[D], e23[D];
        #pragma unroll
        for (int d = 0; d < D; d++) {
            float4 e = F4C(&sEmbT[d * V + v0]);
            e01[d] = pack2(e.x, e.y);
            e23[d] = pack2(e.z, e.w);
        }
        const float4 bl = F4C(&sBlm[v0]);
        const ull bl01 = pack2(bl.x, bl.y);
        const ull bl23 = pack2(bl.z, bl.w);

        float* obase = out + (size_t)item_base * (N * V) + v0;
        const float* xf = sXf[w];

        for (int r = 0; r < IPW * N; r++) {
            float4 xa = F4C(&xf[r * D]);       // broadcast reads
            float4 xb = F4C(&xf[r * D + 4]);
            float4 xc = F4C(&xf[r * D + 8]);
            const float xr[D] = {xa.x, xa.y, xa.z, xa.w,
                                 xb.x, xb.y, xb.z, xb.w,
                                 xc.x, xc.y, xc.z, xc.w};
            ull a01 = bl01, a23 = bl23;
            #pragma unroll
            for (int d = 0; d < D; d++) {
                const ull xv2 = pack2(xr[d], xr[d]);
                ffma2(a01, xv2, e01[d]);
                ffma2(a23, xv2, e23[d]);
            }
            float4 acc;
            unpack2(a01, acc.x, acc.y);
            unpack2(a23, acc.z, acc.w);
            F4(&obase[(size_t)r * V]) = acc;   // coalesced 512B per warp-row
        }
    }
}

}  // namespace

extern "C" void kernel_launch(void* const* d_in, const int* in_sizes, int n_in,
                              void* d_out, int out_size)
{
    const int*   x     = (const int*)  d_in[0];
    const float* embed = (const float*)d_in[1];
    const float* pos   = (const float*)d_in[2];
    const float* Wq    = (const float*)d_in[3];
    const float* bq    = (const float*)d_in[4];
    const float* Wk    = (const float*)d_in[5];
    const float* bk    = (const float*)d_in[6];
    const float* Wv    = (const float*)d_in[7];
    const float* bv    = (const float*)d_in[8];
    const float* Wo    = (const float*)d_in[9];
    const float* bo    = (const float*)d_in[10];
    const float* W1    = (const float*)d_in[11];
    const float* b1    = (const float*)d_in[12];
    const float* W2    = (const float*)d_in[13];
    const float* b2    = (const float*)d_in[14];
    const float* blm   = (const float*)d_in[15];
    float* out = (float*)d_out;

    const int batch  = in_sizes[0] / N;              // 32768
    const int blocks = batch / ITEMS_PER_BLOCK;      // 1024

    tiny_transformer_kernel<<<blocks, THREADS>>>(
        x, embed, pos, Wq, bq, Wk, bk, Wv, bv, Wo, bo,
        W1, b1, W2, b2, blm, out);
}

// round 5
// speedup vs baseline: 2.7169x; 1.0038x over previous
#include <cuda_runtime.h>

namespace {

constexpr int N = 8;      // seq len
constexpr int D = 12;     // embed dim
constexpr int F = 24;     // ff dim
constexpr int V = 128;    // vocab
constexpr int WARPS = 8;  // warps per block
constexpr int IPW = 4;    // items per warp (8 lanes each)
constexpr int THREADS = WARPS * 32;
constexpr int ITEMS_PER_BLOCK = WARPS * IPW;   // 32

#define F4C(p) (*reinterpret_cast<const float4*>(p))
#define F4(p)  (*reinterpret_cast<float4*>(p))

using ull = unsigned long long;

__device__ __forceinline__ ull pack2(float x, float y) {
    ull p; asm("mov.b64 %0, {%1, %2};" : "=l"(p) : "f"(x), "f"(y)); return p;
}
__device__ __forceinline__ void unpack2(ull p, float& x, float& y) {
    asm("mov.b64 {%0, %1}, %2;" : "=f"(x), "=f"(y) : "l"(p));
}
__device__ __forceinline__ void ffma2(ull& d, ull a, ull b) {
    asm("fma.rn.f32x2 %0, %1, %2, %0;" : "+l"(d) : "l"(a), "l"(b));
}

__global__ __launch_bounds__(THREADS, 3)
void tiny_transformer_kernel(
    const int*   __restrict__ x,
    const float* __restrict__ embed,
    const float* __restrict__ pos,
    const float* __restrict__ Wq, const float* __restrict__ bq,
    const float* __restrict__ Wk, const float* __restrict__ bk,
    const float* __restrict__ Wv, const float* __restrict__ bv,
    const float* __restrict__ Wo, const float* __restrict__ bo,
    const float* __restrict__ W1, const float* __restrict__ b1,
    const float* __restrict__ W2, const float* __restrict__ b2,
    const float* __restrict__ blm,
    float* __restrict__ out)
{
    // ---- packed (f32x2) weights, e-major: pW[e][p] = (W[2p][e], W[2p+1][e]) ----
    __shared__ __align__(16) ull pWq[D * 6], pWk[D * 6], pWv[D * 6], pWo[D * 6];
    __shared__ __align__(16) ull pW1[D * 12];          // F=24 -> 12 output pairs
    __shared__ __align__(16) ull pW2[F * 6];           // K=24, 6 output pairs
    __shared__ __align__(16) ull pBq[6], pBk[6], pBv[6], pBo[6], pB2[6], pB1[12];
    __shared__ __align__(16) float sEmbT[D * V];       // transposed [d][v] for logits
    __shared__ __align__(16) float sBlm[V];
    // final hidden states handed to the logits phase: [warp][row][12]
    __shared__ __align__(16) float sXf[WARPS][IPW * N * D];

    const int tid = threadIdx.x;

    // ---- cooperative staging ----
    for (int i = tid; i < D * V; i += THREADS) {
        int d = i >> 7, v = i & 127;
        sEmbT[i] = embed[v * D + d];
    }
    for (int i = tid; i < D * 6; i += THREADS) {
        int e = i / 6, p = i % 6;
        pWq[i] = pack2(Wq[(2*p)   * D + e], Wq[(2*p+1) * D + e]);
        pWk[i] = pack2(Wk[(2*p)   * D + e], Wk[(2*p+1) * D + e]);
        pWv[i] = pack2(Wv[(2*p)   * D + e], Wv[(2*p+1) * D + e]);
        pWo[i] = pack2(Wo[(2*p)   * D + e], Wo[(2*p+1) * D + e]);
    }
    for (int i = tid; i < D * 12; i += THREADS) {
        int e = i / 12, p = i % 12;
        pW1[i] = pack2(W1[(2*p) * D + e], W1[(2*p+1) * D + e]);
    }
    for (int i = tid; i < F * 6; i += THREADS) {
        int f = i / 6, p = i % 6;
        pW2[i] = pack2(W2[(2*p) * F + f], W2[(2*p+1) * F + f]);
    }
    if (tid < 6) {
        pBq[tid] = pack2(bq[2*tid], bq[2*tid+1]);
        pBk[tid] = pack2(bk[2*tid], bk[2*tid+1]);
        pBv[tid] = pack2(bv[2*tid], bv[2*tid+1]);
        pBo[tid] = pack2(bo[2*tid], bo[2*tid+1]);
        pB2[tid] = pack2(b2[2*tid], b2[2*tid+1]);
    }
    if (tid < 12) pB1[tid] = pack2(b1[2*tid], b1[2*tid+1]);
    for (int i = tid; i < V; i += THREADS) sBlm[i] = blm[i];
    __syncthreads();

    const int w    = tid >> 5;
    const int lane = tid & 31;
    const int n    = lane & 7;            // token index within item
    const int item_base = blockIdx.x * ITEMS_PER_BLOCK + w * IPW;

    // ---- phase 1: X = embed[x] + pos (registers; coalesced token load) ----
    const int tok = __ldg(&x[item_base * N + lane]);
    float X[D];
    {
        const float4* e4 = reinterpret_cast<const float4*>(embed);
        const float4* p4 = reinterpret_cast<const float4*>(pos);
        #pragma unroll
        for (int c = 0; c < 3; c++) {
            float4 e = __ldg(&e4[tok * 3 + c]);
            float4 p = __ldg(&p4[n * 3 + c]);
            X[4*c+0] = e.x + p.x; X[4*c+1] = e.y + p.y;
            X[4*c+2] = e.z + p.z; X[4*c+3] = e.w + p.w;
        }
    }

    // ---- phase 2: Q,K,V per token (packed pairs of outputs) ----
    float Qr[D], Kr[D], Vr[D];
    {
        ull q2[6], k2[6], v2[6];
        #pragma unroll
        for (int p = 0; p < 6; p++) { q2[p] = pBq[p]; k2[p] = pBk[p]; v2[p] = pBv[p]; }
        #pragma unroll
        for (int e = 0; e < D; e++) {
            const ull xp = pack2(X[e], X[e]);
            const ulonglong2* wq = reinterpret_cast<const ulonglong2*>(&pWq[e * 6]);
            const ulonglong2* wk = reinterpret_cast<const ulonglong2*>(&pWk[e * 6]);
            const ulonglong2* wv = reinterpret_cast<const ulonglong2*>(&pWv[e * 6]);
            ulonglong2 qa = wq[0], qb = wq[1], qc = wq[2];
            ffma2(q2[0], xp, qa.x); ffma2(q2[1], xp, qa.y);
            ffma2(q2[2], xp, qb.x); ffma2(q2[3], xp, qb.y);
            ffma2(q2[4], xp, qc.x); ffma2(q2[5], xp, qc.y);
            ulonglong2 ka = wk[0], kb = wk[1], kc = wk[2];
            ffma2(k2[0], xp, ka.x); ffma2(k2[1], xp, ka.y);
            ffma2(k2[2], xp, kb.x); ffma2(k2[3], xp, kb.y);
            ffma2(k2[4], xp, kc.x); ffma2(k2[5], xp, kc.y);
            ulonglong2 va = wv[0], vb = wv[1], vc = wv[2];
            ffma2(v2[0], xp, va.x); ffma2(v2[1], xp, va.y);
            ffma2(v2[2], xp, vb.x); ffma2(v2[3], xp, vb.y);
            ffma2(v2[4], xp, vc.x); ffma2(v2[5], xp, vc.y);
        }
        #pragma unroll
        for (int p = 0; p < 6; p++) {
            unpack2(q2[p], Qr[2*p], Qr[2*p+1]);
            unpack2(k2[p], Kr[2*p], Kr[2*p+1]);
            unpack2(v2[p], Vr[2*p], Vr[2*p+1]);
        }
    }

    // ---- phase 3: scores via width-8 shuffles ----
    float S[N];
    {
        const float inv_scale = 0.28867513459481287f;  // 1/sqrt(12)
        #pragma unroll
        for (int m = 0; m < N; m++) {
            float acc = 0.f;
            #pragma unroll
            for (int e = 0; e < D; e++)
                acc += Qr[e] * __shfl_sync(0xffffffffu, Kr[e], m, 8);
            S[m] = (m <= n) ? acc * inv_scale : -1e30f;
        }
    }

    // ---- phase 4: softmax ----
    {
        float mx = S[0];
        #pragma unroll
        for (int m = 1; m < N; m++) mx = fmaxf(mx, S[m]);
        float sum = 0.f;
        #pragma unroll
        for (int m = 0; m < N; m++) { S[m] = __expf(S[m] - mx); sum += S[m]; }
        const float inv = 1.f / sum;
        #pragma unroll
        for (int m = 0; m < N; m++) S[m] *= inv;
    }

    // ---- phase 5: A = softmax @ V via shuffles ----
    float A[D];
    #pragma unroll
    for (int e = 0; e < D; e++) A[e] = 0.f;
    #pragma unroll
    for (int m = 0; m < N; m++) {
        const float s = S[m];
        #pragma unroll
        for (int e = 0; e < D; e++)
            A[e] += s * __shfl_sync(0xffffffffu, Vr[e], m, 8);
    }

    // ---- phase 6: X += A @ Wo^T + bo (packed) ----
    {
        ull o2[6];
        #pragma unroll
        for (int p = 0; p < 6; p++) o2[p] = pBo[p];
        #pragma unroll
        for (int e = 0; e < D; e++) {
            const ull ap = pack2(A[e], A[e]);
            const ulonglong2* wo = reinterpret_cast<const ulonglong2*>(&pWo[e * 6]);
            ulonglong2 oa = wo[0], ob = wo[1], oc = wo[2];
            ffma2(o2[0], ap, oa.x); ffma2(o2[1], ap, oa.y);
            ffma2(o2[2], ap, ob.x); ffma2(o2[3], ap, ob.y);
            ffma2(o2[4], ap, oc.x); ffma2(o2[5], ap, oc.y);
        }
        #pragma unroll
        for (int p = 0; p < 6; p++) {
            float u, v; unpack2(o2[p], u, v);
            X[2*p] += u; X[2*p+1] += v;
        }
    }

    // ---- phase 7: H = relu(X @ W1^T + b1) (packed, 12 output pairs) ----
    float H[F];
    {
        ull h2[12];
        #pragma unroll
        for (int p = 0; p < 12; p++) h2[p] = pB1[p];
        #pragma unroll
        for (int e = 0; e < D; e++) {
            const ull xp = pack2(X[e], X[e]);
            const ulonglong2* w1 = reinterpret_cast<const ulonglong2*>(&pW1[e * 12]);
            #pragma unroll
            for (int q = 0; q < 6; q++) {
                ulonglong2 ww = w1[q];
                ffma2(h2[2*q],   xp, ww.x);
                ffma2(h2[2*q+1], xp, ww.y);
            }
        }
        #pragma unroll
        for (int p = 0; p < 12; p++) {
            float u, v; unpack2(h2[p], u, v);
            H[2*p]   = fmaxf(u, 0.f);
            H[2*p+1] = fmaxf(v, 0.f);
        }
    }

    // ---- phase 8: X += H @ W2^T + b2 (packed) ----
    {
        ull x2[6];
        #pragma unroll
        for (int p = 0; p < 6; p++) x2[p] = pB2[p];
        #pragma unroll
        for (int f = 0; f < F; f++) {
            const ull hp = pack2(H[f], H[f]);
            const ulonglong2* w2 = reinterpret_cast<const ulonglong2*>(&pW2[f * 6]);
            ulonglong2 wa = w2[0], wb = w2[1], wc = w2[2];
            ffma2(x2[0], hp, wa.x); ffma2(x2[1], hp, wa.y);
            ffma2(x2[2], hp, wb.x); ffma2(x2[3], hp, wb.y);
            ffma2(x2[4], hp, wc.x); ffma2(x2[5], hp, wc.y);
        }
        #pragma unroll
        for (int p = 0; p < 6; p++) {
            float u, v; unpack2(x2[p], u, v);
            X[2*p] += u; X[2*p+1] += v;
        }
    }

    // ---- hand off final X to warp-wide logits phase ----
    {
        float* dst = &sXf[w][lane * D];
        F4(dst)     = make_float4(X[0], X[1], X[2],  X[3]);
        F4(dst + 4) = make_float4(X[4], X[5], X[6],  X[7]);
        F4(dst + 8) = make_float4(X[8], X[9], X[10], X[11]);
    }
    __syncwarp();

    // ---- phase 9: logits = Xf @ embed^T + b_lm (warp-wide, 32 rows) ----
    {
        const int v0 = lane * 4;
        ull e01[D], e23[D];
        #pragma unroll
        for (int d = 0; d < D; d++) {
            float4 e = F4C(&sEmbT[d * V + v0]);
            e01[d] = pack2(e.x, e.y);
            e23[d] = pack2(e.z, e.w);
        }
        const float4 bl = F4C(&sBlm[v0]);
        const ull bl01 = pack2(bl.x, bl.y);
        const ull bl23 = pack2(bl.z, bl.w);

        float* obase = out + (size_t)item_base * (N * V) + v0;
        const float* xf = sXf[w];

        for (int r = 0; r < IPW * N; r++) {
            float4 xa = F4C(&xf[r * D]);       // broadcast reads
            float4 xb = F4C(&xf[r * D + 4]);
            float4 xc = F4C(&xf[r * D + 8]);
            const float xr[D] = {xa.x, xa.y, xa.z, xa.w,
                                 xb.x, xb.y, xb.z, xb.w,
                                 xc.x, xc.y, xc.z, xc.w};
            ull a01 = bl01, a23 = bl23;
            #pragma unroll
            for (int d = 0; d < D; d++) {
                const ull xv2 = pack2(xr[d], xr[d]);
                ffma2(a01, xv2, e01[d]);
                ffma2(a23, xv2, e23[d]);
            }
            float4 acc;
            unpack2(a01, acc.x, acc.y);
            unpack2(a23, acc.z, acc.w);
            F4(&obase[(size_t)r * V]) = acc;   // coalesced 512B per warp-row
        }
    }
}

}  // namespace

extern "C" void kernel_launch(void* const* d_in, const int* in_sizes, int n_in,
                              void* d_out, int out_size)
{
    const int*   x     = (const int*)  d_in[0];
    const float* embed = (const float*)d_in[1];
    const float* pos   = (const float*)d_in[2];
    const float* Wq    = (const float*)d_in[3];
    const float* bq    = (const float*)d_in[4];
    const float* Wk    = (const float*)d_in[5];
    const float* bk    = (const float*)d_in[6];
    const float* Wv    = (const float*)d_in[7];
    const float* bv    = (const float*)d_in[8];
    const float* Wo    = (const float*)d_in[9];
    const float* bo    = (const float*)d_in[10];
    const float* W1    = (const float*)d_in[11];
    const float* b1    = (const float*)d_in[12];
    const float* W2    = (const float*)d_in[13];
    const float* b2    = (const float*)d_in[14];
    const float* blm   = (const float*)d_in[15];
    float* out = (float*)d_out;

    const int batch  = in_sizes[0] / N;              // 32768
    const int blocks = batch / ITEMS_PER_BLOCK;      // 1024

    tiny_transformer_kernel<<<blocks, THREADS>>>(
        x, embed, pos, Wq, bq, Wk, bk, Wv, bv, Wo, bo,
        W1, b1, W2, b2, blm, out);
}